// round 8
// baseline (speedup 1.0000x reference)
#include <cuda_runtime.h>
#include <cstdint>
#include <cstddef>

#define Bn 32
#define Tn 512
#define In 512
#define Hn 512
#define Gn 1536
#define DIRSZ (Tn*Gn*Bn)   /* 25,165,824 floats per direction */
#define NCTA_DIR 64        /* CTAs per direction; 128 total <= 148 SMs */

// Static device scratch (no cudaMalloc allowed anywhere)
__device__ float g_gi[2ull * DIRSZ];                       // [dir][step][g][b] (~201 MB)
__device__ __align__(16) float g_hbuf[2][2][Hn * Bn];      // [dir][buf]: float4-packed [k4][b][4]
struct __align__(128) BarPad { volatile unsigned v; unsigned pad[31]; };
__device__ BarPad g_bar2[2];                               // per-direction barrier counters

// ---------------------------------------------------------------------------
// packed fp32x2 FMA (Blackwell FFMA2): d.lo += a.lo*b.lo ; d.hi += a.hi*b.hi
// ---------------------------------------------------------------------------
__device__ __forceinline__ void ffma2(float2 &d, float2 a, float2 b) {
    unsigned long long dd = *reinterpret_cast<unsigned long long*>(&d);
    unsigned long long aa = *reinterpret_cast<unsigned long long*>(&a);
    unsigned long long bb = *reinterpret_cast<unsigned long long*>(&b);
    asm("fma.rn.f32x2 %0, %1, %2, %0;" : "+l"(dd) : "l"(aa), "l"(bb));
    *reinterpret_cast<unsigned long long*>(&d) = dd;
}

// ---------------------------------------------------------------------------
// Phase 1: gi[g][b] for one token t = W_ih @ x_t^T.
// CTA: one t, one 256-wide g tile, one dir. Thread tile 8g x 4b. K chunks of 32.
// dir==0 writes slot t. dir==1 writes PER-BATCH permuted slot
//   tw = (t < L_b) ? L_b-1-t : t   (bijection) so the recurrence reads slot tau
// with the same coalesced pattern as forward. Invalid slots hold finite garbage
// that the recurrence's valid-mask discards (rewritten deterministically every
// launch, so replays are bit-identical).
// ---------------------------------------------------------------------------
__global__ void __launch_bounds__(256) gi_gemm(const float* __restrict__ x,
                                               const float* __restrict__ Wf,
                                               const float* __restrict__ Wb,
                                               const int*   __restrict__ lengths)
{
    if (threadIdx.x == 0 && blockIdx.x == 0 && blockIdx.y == 0 && blockIdx.z == 0) {
        g_bar2[0].v = 0u;   // reset per-direction barriers for the recurrence
        g_bar2[1].v = 0u;
    }

    const int t     = blockIdx.x;
    const int gbase = blockIdx.y * 256;
    const int dir   = blockIdx.z;
    const float* __restrict__ W = dir ? Wb : Wf;

    __shared__ float4 Ws4[256 * 9];   // [row][k4], pitch 9 float4 (pad kills conflicts)
    __shared__ float4 Xs4[32 * 9];

    const int tid = threadIdx.x;
    const int g0  = (tid >> 3) << 3;  // 32 g-octets
    const int b0  = (tid & 7) << 2;   // 8 b-quads

    // per-batch permuted step slot for backward writes
    int tw[4];
    #pragma unroll
    for (int v = 0; v < 4; ++v) {
        int L = lengths[b0 + v];
        tw[v] = (t < L) ? (L - 1 - t) : t;
    }

    float2 a[8][4];
    #pragma unroll
    for (int u = 0; u < 8; ++u)
        #pragma unroll
        for (int v = 0; v < 4; ++v) a[u][v] = make_float2(0.f, 0.f);

    const int xrow = tid >> 3;        // 0..31 (batch)
    const int xk4  = tid & 7;

    for (int kb = 0; kb < 512; kb += 32) {
        __syncthreads();
        #pragma unroll
        for (int u = 0; u < 8; ++u) {
            int f = tid + 256 * u;
            int row = f >> 3, k4 = f & 7;
            Ws4[row * 9 + k4] =
                *(const float4*)&W[(size_t)(gbase + row) * 512 + kb + k4 * 4];
        }
        Xs4[xrow * 9 + xk4] =
            *(const float4*)&x[((size_t)xrow * Tn + t) * 512 + kb + xk4 * 4];
        __syncthreads();

        #pragma unroll
        for (int k4 = 0; k4 < 8; ++k4) {
            float4 xv[4];
            #pragma unroll
            for (int v = 0; v < 4; ++v) xv[v] = Xs4[(b0 + v) * 9 + k4];
            #pragma unroll
            for (int u = 0; u < 8; ++u) {
                float4 wv = Ws4[(g0 + u) * 9 + k4];
                #pragma unroll
                for (int v = 0; v < 4; ++v) {
                    ffma2(a[u][v], make_float2(wv.x, wv.y), make_float2(xv[v].x, xv[v].y));
                    ffma2(a[u][v], make_float2(wv.z, wv.w), make_float2(xv[v].z, xv[v].w));
                }
            }
        }
    }

    if (dir == 0) {
        float* outp = g_gi + ((size_t)t * Gn + gbase) * Bn;
        #pragma unroll
        for (int u = 0; u < 8; ++u) {
            float4 o;
            o.x = a[u][0].x + a[u][0].y;
            o.y = a[u][1].x + a[u][1].y;
            o.z = a[u][2].x + a[u][2].y;
            o.w = a[u][3].x + a[u][3].y;
            *(float4*)(outp + (size_t)(g0 + u) * Bn + b0) = o;
        }
    } else {
        #pragma unroll
        for (int u = 0; u < 8; ++u) {
            int g = gbase + g0 + u;
            #pragma unroll
            for (int v = 0; v < 4; ++v) {
                float o = a[u][v].x + a[u][v].y;
                g_gi[(size_t)DIRSZ + ((size_t)tw[v] * Gn + g) * Bn + (b0 + v)] = o;
            }
        }
    }
}

// ---------------------------------------------------------------------------
// Phase 2: persistent recurrence. 128 CTAs (64/dir) <= 148 SMs, 72 KB smem/CTA
// -> wave-1 co-residency guaranteed, so the counter barriers cannot deadlock.
// The two directions are data-independent, so each syncs only its own 64 CTAs
// (separate padded counters: half the atomic fan-in, no cross-dir skew coupling).
// Phase A: warp w = K-slice [64w,64w+64), lane = batch; all 24 gate-rows in SMEM;
//          h read once per CTA per step straight from L2 (__ldcg float4).
// Phase B: warp w = output column col0+w, lane = batch; reduce 8 psum partials.
// All cross-CTA h traffic is .cg (L2 = coherence point; no stale L1).
// ---------------------------------------------------------------------------
__global__ void __launch_bounds__(256) gru_rec(const float* __restrict__ Whf,
                                               const float* __restrict__ Whb,
                                               const int*   __restrict__ lengths,
                                               float*       __restrict__ out)
{
    extern __shared__ float smdyn[];
    float4* Wsh4 = (float4*)smdyn;            // 24 rows x 128 k4 = 48 KB
    float*  psum = smdyn + 24 * 128 * 4;      // [8 warps][24 rows][32 b] = 24 KB

    const int tid  = threadIdx.x;
    const int w    = tid >> 5;                // warp id
    const int lane = tid & 31;                // batch b
    const int dir  = blockIdx.x >> 6;
    const int chunk= blockIdx.x & 63;
    const int col0 = chunk * 8;
    const int j    = col0 + w;                // phase-B column for this warp
    volatile unsigned* bar = &g_bar2[dir].v;

    // Load 24 W_hh rows (3 gates x 8 cols) once: Wsh4[row*128 + k4]
    const float* Wsrc = dir ? Whb : Whf;
    #pragma unroll
    for (int u = 0; u < 12; ++u) {
        int idx = tid + 256 * u;              // == row*128 + k4
        int row = idx >> 7, k4 = idx & 127;
        int grow = (row >> 3) * 512 + col0 + (row & 7);
        Wsh4[idx] = *(const float4*)&Wsrc[(size_t)grow * 512 + k4 * 4];
    }
    const int Lb = lengths[lane];
    __syncthreads();

    unsigned target = 0;
    for (int tau = 0; tau < Tn; ++tau) {
        // ---- prefetch this step's gi + hprev (overlaps phase-A compute) ----
        const float* gp = g_gi + (size_t)dir * DIRSZ + ((size_t)tau * Gn + j) * Bn + lane;
        float ir  = __ldcs(gp);
        float ii  = __ldcs(gp + 512 * Bn);
        float inn = __ldcs(gp + 1024 * Bn);
        const float* hb_cur = g_hbuf[dir][tau & 1];
        float hprev = 0.f;
        if (tau > 0) hprev = __ldcg(&hb_cur[((j >> 2) * 32 + lane) * 4 + (j & 3)]);

        // ---- phase A: partial dot products over this warp's K-slice ----
        float2 acc[24];
        #pragma unroll
        for (int r = 0; r < 24; ++r) acc[r] = make_float2(0.f, 0.f);
        if (tau > 0) {
            const float4* hb4 = (const float4*)hb_cur;
            #pragma unroll 4
            for (int kk = 0; kk < 16; ++kk) {
                int k4 = 16 * w + kk;
                float4 hv = __ldcg(hb4 + (size_t)k4 * 32 + lane);
                const float4* wc = Wsh4 + k4;
                #pragma unroll
                for (int r = 0; r < 24; ++r) {
                    float4 wv = wc[(size_t)r * 128];   // broadcast LDS
                    ffma2(acc[r], make_float2(wv.x, wv.y), make_float2(hv.x, hv.y));
                    ffma2(acc[r], make_float2(wv.z, wv.w), make_float2(hv.z, hv.w));
                }
            }
        }
        float* ps = psum + (w * 24) * 32 + lane;
        #pragma unroll
        for (int r = 0; r < 24; ++r) ps[r * 32] = acc[r].x + acc[r].y;
        __syncthreads();

        // ---- phase B: reduce partials, gates, write h + seq output ----
        float ghr = 0.f, ghi = 0.f, ghn = 0.f;
        if (tau > 0) {
            #pragma unroll
            for (int pw = 0; pw < 8; ++pw) {
                ghr += psum[(pw * 24 +      w) * 32 + lane];
                ghi += psum[(pw * 24 +  8 + w) * 32 + lane];
                ghn += psum[(pw * 24 + 16 + w) * 32 + lane];
            }
        }
        float gr = 1.f / (1.f + __expf(-ir));
        float gz = 1.f / (1.f + __expf(-ii));
        float fz = gz * (1.f - gz);
        float gn = 2.f / (1.f + __expf(-2.f * inn)) - 1.f;   // tanh, overflow-safe
        float fn = 1.f - gn * gn;

        float hnew = fn * (1.f - gz) * gr * ghn - fz * gn * ghi + gz * hprev;
        if (tau == 0) hnew += (1.f - gz) * gn;               // init term (h==0, gh==0 then)

        int  tok   = dir ? (Lb - 1 - tau) : tau;             // original token index
        bool valid = dir ? (tok >= 0) : (tau < Lb);
        float hout = valid ? hnew : hprev;

        __stcg(&g_hbuf[dir][(tau + 1) & 1][((j >> 2) * 32 + lane) * 4 + (j & 3)], hout);
        if (dir == 0) {
            // forward writes every step (masked steps carry h -> matches reference)
            __stcg(out + ((size_t)(lane * Tn + tau)) * 1024 + j, hout);
        } else if (tok >= 0) {
            __stcg(out + ((size_t)(lane * Tn + tok)) * 1024 + 512 + j, hout);
        }

        // ---- per-direction barrier (monotonic counter; bar.sync -> fence ->
        //      atomic release chain; .cg data lands at L2 so spinners see it) ----
        __syncthreads();
        target += NCTA_DIR;
        if (tid == 0) {
            __threadfence();
            atomicAdd((unsigned*)bar, 1u);
            while (*bar < target) { }
            __threadfence();
        }
        __syncthreads();
    }
}

// ---------------------------------------------------------------------------
// Phase 3: epilogue — cat_hidden + backward padding region (= final bwd hidden)
// ---------------------------------------------------------------------------
__global__ void __launch_bounds__(256) gru_epi(const int* __restrict__ lengths,
                                               float* __restrict__ out)
{
    __shared__ float hbs[512];
    const int b   = blockIdx.x;
    const int tid = threadIdx.x;

    // cat_hidden: final h lives in buffer 0 ((511+1)&1 == 0)
    float* cat = out + (size_t)Bn * Tn * 1024;
    for (int c = tid; c < 1024; c += 256) {
        int d  = c >> 9;
        int jj = c & 511;
        cat[(size_t)b * 1024 + c] = g_hbuf[d][0][((jj >> 2) * 32 + b) * 4 + (jj & 3)];
    }
    for (int jj = tid; jj < 512; jj += 256)
        hbs[jj] = g_hbuf[1][0][((jj >> 2) * 32 + b) * 4 + (jj & 3)];
    __syncthreads();

    const int L = lengths[b];
    const int n = (Tn - L) * 512;
    for (int idx = tid; idx < n; idx += 256) {
        int s  = L + (idx >> 9);
        int jj = idx & 511;
        out[((size_t)(b * Tn + s)) * 1024 + 512 + jj] = hbs[jj];
    }
}

// ---------------------------------------------------------------------------
extern "C" void kernel_launch(void* const* d_in, const int* in_sizes, int n_in,
                              void* d_out, int out_size)
{
    const float* x       = (const float*)d_in[0];
    const int*   lengths = (const int*)  d_in[1];
    const float* Wif     = (const float*)d_in[2];
    const float* Whf     = (const float*)d_in[3];
    const float* Wib     = (const float*)d_in[4];
    const float* Whb     = (const float*)d_in[5];
    float* out = (float*)d_out;

    dim3 gg(Tn, 6, 2);
    gi_gemm<<<gg, 256>>>(x, Wif, Wib, lengths);

    const int shmem = 24 * 128 * 16 + 8 * 24 * 32 * 4;   // 48 KB W + 24 KB psum = 73,728 B
    cudaFuncSetAttribute(gru_rec, cudaFuncAttributeMaxDynamicSharedMemorySize, shmem);
    gru_rec<<<2 * NCTA_DIR, 256, shmem>>>(Whf, Whb, lengths, out);

    gru_epi<<<Bn, 256>>>(lengths, out);
}

// round 11
// speedup vs baseline: 1.2570x; 1.2570x over previous
#include <cuda_runtime.h>
#include <cstdint>
#include <cstddef>

#define Bn 32
#define Tn 512
#define In 512
#define Hn 512
#define Gn 1536
#define DIRSZ (Tn*Gn*Bn)   /* 25,165,824 floats per direction */
#define NCTA_DIR 64        /* CTAs per direction; 128 total <= 148 SMs */

// Static device scratch (no cudaMalloc allowed anywhere)
__device__ float g_gi[2ull * DIRSZ];                       // [dir][step][g][b] (~201 MB)
__device__ __align__(16) float g_hbuf[2][2][Hn * Bn];      // [dir][buf]: float4-packed [k4][b][4]
struct __align__(128) BarPad { unsigned v; unsigned pad[31]; };
__device__ BarPad g_bar2[2];                               // per-direction barrier counters

// ---------------------------------------------------------------------------
// packed fp32x2 FMA (Blackwell FFMA2)
// ---------------------------------------------------------------------------
__device__ __forceinline__ void ffma2(float2 &d, float2 a, float2 b) {
    unsigned long long dd = *reinterpret_cast<unsigned long long*>(&d);
    unsigned long long aa = *reinterpret_cast<unsigned long long*>(&a);
    unsigned long long bb = *reinterpret_cast<unsigned long long*>(&b);
    asm("fma.rn.f32x2 %0, %1, %2, %0;" : "+l"(dd) : "l"(aa), "l"(bb));
    *reinterpret_cast<unsigned long long*>(&d) = dd;
}

// release/acquire grid-barrier primitives (cheaper than membar.gl pairs)
__device__ __forceinline__ void bar_arrive(unsigned* p) {
    asm volatile("red.release.gpu.global.add.u32 [%0], 1;" :: "l"(p) : "memory");
}
__device__ __forceinline__ unsigned bar_acq(const unsigned* p) {
    unsigned v;
    asm volatile("ld.acquire.gpu.global.u32 %0, [%1];" : "=r"(v) : "l"(p) : "memory");
    return v;
}

// ---------------------------------------------------------------------------
// Phase 1: gi GEMM. CTA: one t, 256-wide g tile, one dir. Thread tile 8g x 4b.
// CONFLICT FIX (R8 ncu: l1tex 83.7%): thread owns g = (tid>>3) + 32u and
// b = (tid&7) + 8v, so warp lane-groups read CONSECUTIVE smem rows (144B pitch
// -> 4-bank stagger, conflict-free) instead of stride-8 rows (0 mod 128B ->
// 4-way conflict on every inner-loop LDS).
// dir==1 writes per-batch permuted slot tw = (t<L_b)? L_b-1-t : t (bijection).
// ---------------------------------------------------------------------------
__global__ void __launch_bounds__(256) gi_gemm(const float* __restrict__ x,
                                               const float* __restrict__ Wf,
                                               const float* __restrict__ Wb,
                                               const int*   __restrict__ lengths)
{
    if (threadIdx.x == 0 && blockIdx.x == 0 && blockIdx.y == 0 && blockIdx.z == 0) {
        g_bar2[0].v = 0u;   // reset per-direction barriers for the recurrence
        g_bar2[1].v = 0u;
    }

    const int t     = blockIdx.x;
    const int gbase = blockIdx.y * 256;
    const int dir   = blockIdx.z;
    const float* __restrict__ W = dir ? Wb : Wf;

    __shared__ float4 Ws4[256 * 9];   // [row][k4], pitch 9 float4
    __shared__ float4 Xs4[32 * 9];

    const int tid = threadIdx.x;
    const int g0  = tid >> 3;         // 0..31 : consecutive rows within warp
    const int b0  = tid & 7;          // 0..7  : consecutive rows within warp

    // per-batch permuted step slot for backward writes
    int tw[4];
    #pragma unroll
    for (int v = 0; v < 4; ++v) {
        int L = lengths[b0 + 8 * v];
        tw[v] = (t < L) ? (L - 1 - t) : t;
    }

    float2 a[8][4];
    #pragma unroll
    for (int u = 0; u < 8; ++u)
        #pragma unroll
        for (int v = 0; v < 4; ++v) a[u][v] = make_float2(0.f, 0.f);

    const int xrow = tid >> 3;        // 0..31 (batch)
    const int xk4  = tid & 7;

    for (int kb = 0; kb < 512; kb += 32) {
        __syncthreads();
        #pragma unroll
        for (int u = 0; u < 8; ++u) {
            int f = tid + 256 * u;
            int row = f >> 3, k4 = f & 7;
            Ws4[row * 9 + k4] =
                *(const float4*)&W[(size_t)(gbase + row) * 512 + kb + k4 * 4];
        }
        Xs4[xrow * 9 + xk4] =
            *(const float4*)&x[((size_t)xrow * Tn + t) * 512 + kb + xk4 * 4];
        __syncthreads();

        #pragma unroll
        for (int k4 = 0; k4 < 8; ++k4) {
            float4 xv[4];
            #pragma unroll
            for (int v = 0; v < 4; ++v) xv[v] = Xs4[(b0 + 8 * v) * 9 + k4];
            #pragma unroll
            for (int u = 0; u < 8; ++u) {
                float4 wv = Ws4[(g0 + 32 * u) * 9 + k4];
                #pragma unroll
                for (int v = 0; v < 4; ++v) {
                    ffma2(a[u][v], make_float2(wv.x, wv.y), make_float2(xv[v].x, xv[v].y));
                    ffma2(a[u][v], make_float2(wv.z, wv.w), make_float2(xv[v].z, xv[v].w));
                }
            }
        }
    }

    if (dir == 0) {
        #pragma unroll
        for (int u = 0; u < 8; ++u) {
            int g = gbase + g0 + 32 * u;
            #pragma unroll
            for (int v = 0; v < 4; ++v)
                g_gi[((size_t)t * Gn + g) * Bn + b0 + 8 * v] = a[u][v].x + a[u][v].y;
        }
    } else {
        #pragma unroll
        for (int u = 0; u < 8; ++u) {
            int g = gbase + g0 + 32 * u;
            #pragma unroll
            for (int v = 0; v < 4; ++v)
                g_gi[(size_t)DIRSZ + ((size_t)tw[v] * Gn + g) * Bn + b0 + 8 * v] =
                    a[u][v].x + a[u][v].y;
        }
    }
}

// ---------------------------------------------------------------------------
// Phase 2: persistent recurrence. 128 CTAs (64/dir), per-direction barriers.
// Phase A: warp w = K-slice [64w,64w+64): h preloaded into 16 float4 regs
//          (MLP=16, one L2-latency exposure/step), W rows broadcast from SMEM.
// Phase B: warp w = column col0+w; reduce 8 psum partials; stage hout in SMEM;
//          coalesced out-writes overlap the barrier wait (arrive early).
// ---------------------------------------------------------------------------
__global__ void __launch_bounds__(256) gru_rec(const float* __restrict__ Whf,
                                               const float* __restrict__ Whb,
                                               const int*   __restrict__ lengths,
                                               float*       __restrict__ out)
{
    extern __shared__ float smdyn[];
    float4* Wsh4  = (float4*)smdyn;               // 24 rows x 128 k4 = 48 KB
    float*  psum  = smdyn + 12288;                // [8][24][32] = 24 KB
    float*  stage = smdyn + 12288 + 6144;         // [32 b][9]  (pitch 9: no conflicts)
    int*    sLen  = (int*)(smdyn + 12288 + 6144 + 288);   // [32]

    const int tid  = threadIdx.x;
    const int w    = tid >> 5;                // warp id
    const int lane = tid & 31;                // batch b (phases A/B)
    const int dir  = blockIdx.x >> 6;
    const int chunk= blockIdx.x & 63;
    const int col0 = chunk * 8;
    const int j    = col0 + w;                // phase-B column for this warp
    unsigned* bar  = &g_bar2[dir].v;

    // Load 24 W_hh rows (3 gates x 8 cols) once: Wsh4[row*128 + k4]
    const float* Wsrc = dir ? Whb : Whf;
    #pragma unroll
    for (int u = 0; u < 12; ++u) {
        int idx = tid + 256 * u;              // == row*128 + k4
        int row = idx >> 7, k4 = idx & 127;
        int grow = (row >> 3) * 512 + col0 + (row & 7);
        Wsh4[idx] = *(const float4*)&Wsrc[(size_t)grow * 512 + k4 * 4];
    }
    if (tid < 32) sLen[tid] = lengths[tid];
    const int Lb = lengths[lane];
    __syncthreads();

    // out-writer mapping (between arrive and wait): c = column, ob = batch
    const int oc = tid & 7;
    const int ob = tid >> 3;

    unsigned target = 0;
    for (int tau = 0; tau < Tn; ++tau) {
        // ---- prefetch this step's gi + hprev (consumed ~3K cyc later) ----
        const float* gp = g_gi + (size_t)dir * DIRSZ + ((size_t)tau * Gn + j) * Bn + lane;
        float ir  = __ldcs(gp);
        float ii  = __ldcs(gp + 512 * Bn);
        float inn = __ldcs(gp + 1024 * Bn);
        const float* hb_cur = g_hbuf[dir][tau & 1];
        float hprev = 0.f;
        if (tau > 0) hprev = __ldcg(&hb_cur[((j >> 2) * 32 + lane) * 4 + (j & 3)]);

        // ---- phase A: front-batch ALL 16 h loads (MLP=16), then FFMA2 ----
        float2 acc[24];
        #pragma unroll
        for (int r = 0; r < 24; ++r) acc[r] = make_float2(0.f, 0.f);
        if (tau > 0) {
            const float4* hb4 = (const float4*)hb_cur;
            float4 hreg[16];
            #pragma unroll
            for (int kk = 0; kk < 16; ++kk)
                hreg[kk] = __ldcg(hb4 + (size_t)(16 * w + kk) * 32 + lane);
            #pragma unroll
            for (int kk = 0; kk < 16; ++kk) {
                const float4* wc = Wsh4 + 16 * w + kk;
                #pragma unroll
                for (int r = 0; r < 24; ++r) {
                    float4 wv = wc[(size_t)r * 128];   // warp-uniform broadcast LDS
                    ffma2(acc[r], make_float2(wv.x, wv.y), make_float2(hreg[kk].x, hreg[kk].y));
                    ffma2(acc[r], make_float2(wv.z, wv.w), make_float2(hreg[kk].z, hreg[kk].w));
                }
            }
        }
        float* ps = psum + (w * 24) * 32 + lane;
        #pragma unroll
        for (int r = 0; r < 24; ++r) ps[r * 32] = acc[r].x + acc[r].y;
        __syncthreads();

        // ---- phase B: reduce partials, gates, h update ----
        float ghr = 0.f, ghi = 0.f, ghn = 0.f;
        if (tau > 0) {
            #pragma unroll
            for (int pw = 0; pw < 8; ++pw) {
                ghr += psum[(pw * 24 +      w) * 32 + lane];
                ghi += psum[(pw * 24 +  8 + w) * 32 + lane];
                ghn += psum[(pw * 24 + 16 + w) * 32 + lane];
            }
        }
        float gr = 1.f / (1.f + __expf(-ir));
        float gz = 1.f / (1.f + __expf(-ii));
        float fz = gz * (1.f - gz);
        float gn = 2.f / (1.f + __expf(-2.f * inn)) - 1.f;   // tanh, overflow-safe
        float fn = 1.f - gn * gn;

        float hnew = fn * (1.f - gz) * gr * ghn - fz * gn * ghi + gz * hprev;
        if (tau == 0) hnew += (1.f - gz) * gn;               // init term (h==0, gh==0 then)

        int  tok   = dir ? (Lb - 1 - tau) : tau;
        bool valid = dir ? (tok >= 0) : (tau < Lb);
        float hout = valid ? hnew : hprev;

        __stcg(&g_hbuf[dir][(tau + 1) & 1][((j >> 2) * 32 + lane) * 4 + (j & 3)], hout);
        stage[lane * 9 + w] = hout;           // [b][col] staging for coalesced out

        // ---- arrive EARLY, write out (coalesced) during the wait ----
        __syncthreads();                      // h stores + staging complete
        target += NCTA_DIR;
        if (tid == 0) bar_arrive(bar);

        {
            float v = stage[ob * 9 + oc];
            if (dir == 0) {
                // forward writes every step (masked steps carry h -> matches ref)
                out[((size_t)(ob * Tn + tau)) * 1024 + col0 + oc] = v;
            } else {
                int tkb = sLen[ob] - 1 - tau;
                if (tkb >= 0)
                    out[((size_t)(ob * Tn + tkb)) * 1024 + 512 + col0 + oc] = v;
            }
        }

        if (tid == 0) { while (bar_acq(bar) < target) { } }
        __syncthreads();
    }
}

// ---------------------------------------------------------------------------
// Phase 3: epilogue — cat_hidden + backward padding region (= final bwd hidden)
// ---------------------------------------------------------------------------
__global__ void __launch_bounds__(256) gru_epi(const int* __restrict__ lengths,
                                               float* __restrict__ out)
{
    __shared__ float hbs[512];
    const int b   = blockIdx.x;
    const int tid = threadIdx.x;

    // cat_hidden: final h lives in buffer 0 ((511+1)&1 == 0)
    float* cat = out + (size_t)Bn * Tn * 1024;
    for (int c = tid; c < 1024; c += 256) {
        int d  = c >> 9;
        int jj = c & 511;
        cat[(size_t)b * 1024 + c] = g_hbuf[d][0][((jj >> 2) * 32 + b) * 4 + (jj & 3)];
    }
    for (int jj = tid; jj < 512; jj += 256)
        hbs[jj] = g_hbuf[1][0][((jj >> 2) * 32 + b) * 4 + (jj & 3)];
    __syncthreads();

    const int L = lengths[b];
    const int n = (Tn - L) * 512;
    for (int idx = tid; idx < n; idx += 256) {
        int s  = L + (idx >> 9);
        int jj = idx & 511;
        out[((size_t)(b * Tn + s)) * 1024 + 512 + jj] = hbs[jj];
    }
}

// ---------------------------------------------------------------------------
extern "C" void kernel_launch(void* const* d_in, const int* in_sizes, int n_in,
                              void* d_out, int out_size)
{
    const float* x       = (const float*)d_in[0];
    const int*   lengths = (const int*)  d_in[1];
    const float* Wif     = (const float*)d_in[2];
    const float* Whf     = (const float*)d_in[3];
    const float* Wib     = (const float*)d_in[4];
    const float* Whb     = (const float*)d_in[5];
    float* out = (float*)d_out;

    dim3 gg(Tn, 6, 2);
    gi_gemm<<<gg, 256>>>(x, Wif, Wib, lengths);

    // 48KB W + 24KB psum + stage(288f) + sLen(32i) = 75,008 B
    const int shmem = (12288 + 6144 + 288 + 32) * 4;
    cudaFuncSetAttribute(gru_rec, cudaFuncAttributeMaxDynamicSharedMemorySize, shmem);
    gru_rec<<<2 * NCTA_DIR, 256, shmem>>>(Whf, Whb, lengths, out);

    gru_epi<<<Bn, 256>>>(lengths, out);
}